// round 8
// baseline (speedup 1.0000x reference)
#include <cuda_runtime.h>
#include <cuda_bf16.h>
#include <cstdint>
#include <math.h>

#define TOT   16384
#define NPTS  4096
#define KNN   16
#define HD    128
#define IND   64
#define AP_Q  132    // qkv A buffer pitch (scalar frag loads)
#define P     136    // fused A/W pitch + qkv W pitch

// ---------------- device scratch ------------------------------------------------
__device__ int   g_idx[TOT * KNN];
__device__ float g_t  [TOT * HD];
__device__ float g_q  [TOT * HD];
__device__ float g_kf [TOT * HD];
__device__ float g_v  [TOT * HD];
__device__ float g_agg[TOT * HD];
__device__ float g_part[128 * 2 * HD];
__device__ float g_stats[2 * HD];
__device__ float g_wtf[3 * HD * HD];   // tf32 weights, TRANSPOSED [c][k'] (k permuted)
__device__ unsigned int g_tick1;
__device__ unsigned int g_tick2;

__device__ __forceinline__ float to_tf32(float x) {
    unsigned int r;
    asm("cvt.rna.tf32.f32 %0, %1;" : "=r"(r) : "f"(x));
    return __uint_as_float(r);
}
__device__ __forceinline__ int permk(int k) {          // per-8 k permutation
    return (k & ~7) | ((k & 3) << 1) | ((k >> 2) & 1);
}

__device__ __forceinline__ void cp16(void* dst_smem, const void* src) {
    unsigned int d = (unsigned int)__cvta_generic_to_shared(dst_smem);
    asm volatile("cp.async.cg.shared.global [%0], [%1], 16;\n" :: "r"(d), "l"(src));
}
__device__ __forceinline__ void cp_commit() {
    asm volatile("cp.async.commit_group;\n");
}
template <int N>
__device__ __forceinline__ void cp_wait() {
    asm volatile("cp.async.wait_group %0;\n" :: "n"(N));
}

// ============== weight pre-convert: tf32, transposed [c][k'] =====================
__global__ __launch_bounds__(512) void conv_kernel(const float* __restrict__ Wd2,
                                                   const float* __restrict__ Wg1,
                                                   const float* __restrict__ Wg2) {
    int e = blockIdx.x * 512 + threadIdx.x;            // one source float4 each
    const float* srcs[3] = {Wd2, Wg1, Wg2};
    int m = e / 4096;
    if (m < 3) {
        int idx = e & 4095;
        int k = idx >> 5, c = (idx & 31) * 4;
        float4 v = *(const float4*)&srcs[m][k * 128 + c];
        int kp = permk(k);
        float* dst = g_wtf + m * 16384;
        dst[(c + 0) * 128 + kp] = to_tf32(v.x);
        dst[(c + 1) * 128 + kp] = to_tf32(v.y);
        dst[(c + 2) * 128 + kp] = to_tf32(v.z);
        dst[(c + 3) * 128 + kp] = to_tf32(v.w);
    }
}

// ============================ ball query =========================================
__global__ __launch_bounds__(128) void ball_kernel(const int* __restrict__ coords) {
    __shared__ int sP[NPTS];
    int b = (blockIdx.x * 128) / NPTS;
    int base = b * NPTS;
    for (int j = threadIdx.x; j < NPTS; j += 128) {
        int4 c = *(const int4*)&coords[(size_t)(base + j) * 4];
        sP[j] = c.y | (c.z << 8) | (c.w << 16);
    }
    __syncthreads();
    int qi = blockIdx.x * 128 + threadIdx.x;
    int me = sP[qi - base];
    int qx = me & 255, qy = (me >> 8) & 255, qz = me >> 16;
    int cnt = 0, first = 0;
    int* out = g_idx + (size_t)qi * KNN;
    #pragma unroll 8
    for (int j = 0; j < NPTS; j++) {
        int p = sP[j];
        int dx = qx - (p & 255);
        int dy = qy - ((p >> 8) & 255);
        int dz = qz - (p >> 16);
        int d2 = dx * dx + dy * dy + dz * dz;
        if (d2 <= 100) {
            int gj = base + j;
            out[cnt] = gj;
            if (cnt == 0) first = gj;
            cnt++;
            if (cnt == KNN) break;
        }
    }
    for (int k = cnt; k < KNN; k++) out[k] = first;
}

// ================ t = x @ W_top + b_top, fused BN partials + finalize ===========
__global__ __launch_bounds__(256) void topproj_kernel(const float* __restrict__ x,
                                                      const float* __restrict__ W,
                                                      const float* __restrict__ bias) {
    __shared__ float As[16][128];
    __shared__ float Bs[16][128];
    __shared__ float redS[16][128];
    __shared__ float redSS[16][128];
    __shared__ double dS[2][128];
    __shared__ double dSS[2][128];
    __shared__ bool  sLast;
    int tid = threadIdx.x;
    int ty = tid >> 4, tx = tid & 15;
    int row0 = blockIdx.x * 128;
    float acc[8][8] = {};
    for (int kt = 0; kt < 64; kt += 16) {
        for (int e = tid; e < 512; e += 256) {
            int r = e >> 2, s = e & 3;
            float4 v = *(const float4*)&x[(size_t)(row0 + r) * 64 + kt + s * 4];
            As[s * 4 + 0][r] = v.x; As[s * 4 + 1][r] = v.y;
            As[s * 4 + 2][r] = v.z; As[s * 4 + 3][r] = v.w;
        }
        for (int e = tid; e < 512; e += 256) {
            int k = e >> 5, s = e & 31;
            *(float4*)&Bs[k][s * 4] = *(const float4*)&W[(size_t)(kt + k) * 128 + s * 4];
        }
        __syncthreads();
        #pragma unroll
        for (int k = 0; k < 16; k++) {
            float4 a0 = *(const float4*)&As[k][ty * 8];
            float4 a1 = *(const float4*)&As[k][ty * 8 + 4];
            float4 b0 = *(const float4*)&Bs[k][tx * 8];
            float4 b1 = *(const float4*)&Bs[k][tx * 8 + 4];
            float av[8] = {a0.x, a0.y, a0.z, a0.w, a1.x, a1.y, a1.z, a1.w};
            float bv[8] = {b0.x, b0.y, b0.z, b0.w, b1.x, b1.y, b1.z, b1.w};
            #pragma unroll
            for (int i = 0; i < 8; i++)
                #pragma unroll
                for (int j = 0; j < 8; j++)
                    acc[i][j] += av[i] * bv[j];
        }
        __syncthreads();
    }
    #pragma unroll
    for (int j = 0; j < 8; j++) {
        float b = __ldg(&bias[tx * 8 + j]);
        float s = 0.f, ss = 0.f;
        #pragma unroll
        for (int i = 0; i < 8; i++) {
            float v = acc[i][j] + b;
            g_t[(size_t)(row0 + ty * 8 + i) * 128 + tx * 8 + j] = v;
            s += v; ss += v * v;
        }
        redS[ty][tx * 8 + j] = s;
        redSS[ty][tx * 8 + j] = ss;
    }
    __syncthreads();
    if (tid < 128) {
        float s = 0.f, ss = 0.f;
        #pragma unroll
        for (int u = 0; u < 16; u++) { s += redS[u][tid]; ss += redSS[u][tid]; }
        g_part[blockIdx.x * 256 + tid]       = s;
        g_part[blockIdx.x * 256 + 128 + tid] = ss;
    }
    __threadfence();
    __syncthreads();
    if (tid == 0)
        sLast = (atomicAdd(&g_tick1, 1u) == gridDim.x - 1);
    __syncthreads();
    if (sLast) {
        int c = tid & 127, sub = tid >> 7;   // 2 subs x 128 channels
        double s = 0.0, ss = 0.0;
        for (int b = sub; b < 128; b += 2) {
            s  += (double)g_part[b * 256 + c];
            ss += (double)g_part[b * 256 + 128 + c];
        }
        dS[sub][c] = s; dSS[sub][c] = ss;
        __syncthreads();
        if (tid < 128) {
            double S = dS[0][tid] + dS[1][tid];
            double SS = dSS[0][tid] + dSS[1][tid];
            double m = S / (double)TOT;
            double var = SS / (double)TOT - m * m;
            g_stats[tid]       = (float)m;
            g_stats[128 + tid] = rsqrtf((float)var + 1e-5f);
        }
        if (tid == 0) g_tick1 = 0u;
    }
}

// ================= scalar tf32 mma core (qkv; A pitch AP_Q, W k-major pitch P) ===
__device__ __forceinline__ void gemm_mma_q(const float* __restrict__ A,
                                           const float* __restrict__ W,
                                           float acc[2][4][4],
                                           int wr, int wc, int g, int t) {
    #pragma unroll
    for (int i = 0; i < 2; i++)
        #pragma unroll
        for (int j = 0; j < 4; j++)
            #pragma unroll
            for (int r = 0; r < 4; r++) acc[i][j][r] = 0.f;
    #pragma unroll 4
    for (int kk = 0; kk < 16; kk++) {
        const int k0 = kk * 8;
        unsigned int a[2][4];
        #pragma unroll
        for (int mi = 0; mi < 2; mi++) {
            const float* ap = A + (size_t)(wr * 32 + mi * 16 + g) * AP_Q + k0 + t;
            a[mi][0] = __float_as_uint(ap[0]);
            a[mi][1] = __float_as_uint(ap[8 * AP_Q]);
            a[mi][2] = __float_as_uint(ap[4]);
            a[mi][3] = __float_as_uint(ap[8 * AP_Q + 4]);
        }
        #pragma unroll
        for (int ni = 0; ni < 4; ni++) {
            const float* bp = W + (size_t)(k0 + t) * P + wc * 32 + ni * 8 + g;
            unsigned int b0 = __float_as_uint(bp[0]);
            unsigned int b1 = __float_as_uint(bp[4 * P]);
            #pragma unroll
            for (int mi = 0; mi < 2; mi++) {
                asm volatile(
                    "mma.sync.aligned.m16n8k8.row.col.f32.tf32.tf32.f32 "
                    "{%0,%1,%2,%3}, {%4,%5,%6,%7}, {%8,%9}, {%0,%1,%2,%3};\n"
                    : "+f"(acc[mi][ni][0]), "+f"(acc[mi][ni][1]),
                      "+f"(acc[mi][ni][2]), "+f"(acc[mi][ni][3])
                    : "r"(a[mi][0]), "r"(a[mi][1]), "r"(a[mi][2]), "r"(a[mi][3]),
                      "r"(b0), "r"(b1));
            }
        }
    }
}

// ========== vectorized tf32 mma core (fused; permuted k, A [r][k'] W [c][k']) ====
__device__ __forceinline__ void gemm_mma_v(const float* __restrict__ A,
                                           const float* __restrict__ W,
                                           float acc[2][4][4],
                                           int wr, int wc, int g, int t) {
    #pragma unroll
    for (int i = 0; i < 2; i++)
        #pragma unroll
        for (int j = 0; j < 4; j++)
            #pragma unroll
            for (int r = 0; r < 4; r++) acc[i][j][r] = 0.f;
    #pragma unroll 4
    for (int kk = 0; kk < 16; kk++) {
        const int k0 = kk * 8;
        unsigned int a[2][4];
        #pragma unroll
        for (int mi = 0; mi < 2; mi++) {
            const float* ap = A + (size_t)(wr * 32 + mi * 16 + g) * P + k0 + 2 * t;
            float2 lo = *(const float2*)ap;            // (r, k=t), (r, k=t+4)
            float2 hi = *(const float2*)(ap + 8 * P);  // (r+8, t), (r+8, t+4)
            a[mi][0] = __float_as_uint(lo.x);
            a[mi][1] = __float_as_uint(hi.x);
            a[mi][2] = __float_as_uint(lo.y);
            a[mi][3] = __float_as_uint(hi.y);
        }
        #pragma unroll
        for (int ni = 0; ni < 4; ni++) {
            const float* bp = W + (size_t)(wc * 32 + ni * 8 + g) * P + k0 + 2 * t;
            float2 bb = *(const float2*)bp;            // (k=t, c), (k=t+4, c)
            unsigned int b0 = __float_as_uint(bb.x);
            unsigned int b1 = __float_as_uint(bb.y);
            #pragma unroll
            for (int mi = 0; mi < 2; mi++) {
                asm volatile(
                    "mma.sync.aligned.m16n8k8.row.col.f32.tf32.tf32.f32 "
                    "{%0,%1,%2,%3}, {%4,%5,%6,%7}, {%8,%9}, {%0,%1,%2,%3};\n"
                    : "+f"(acc[mi][ni][0]), "+f"(acc[mi][ni][1]),
                      "+f"(acc[mi][ni][2]), "+f"(acc[mi][ni][3])
                    : "r"(a[mi][0]), "r"(a[mi][1]), "r"(a[mi][2]), "r"(a[mi][3]),
                      "r"(b0), "r"(b1));
            }
        }
    }
}

// ============== q,kf,v = normalize(t) @ {W_phi,W_psi,W_alpha} (mma tf32) =========
__global__ __launch_bounds__(512) void qkv_kernel(const float* __restrict__ g1v,
                                                  const float* __restrict__ be1,
                                                  const float* __restrict__ Wphi,
                                                  const float* __restrict__ Wpsi,
                                                  const float* __restrict__ Walpha) {
    extern __shared__ float sm[];
    float* BufA = sm;                    // [128][AP_Q]
    float* BufW = BufA + 128 * AP_Q;     // [128][P] k-major
    __shared__ float sScale[128], sShift[128];
    int tid = threadIdx.x;
    if (tid < 128) {
        float m = g_stats[tid], is = g_stats[128 + tid];
        float sc = is * g1v[tid];
        sScale[tid] = sc;
        sShift[tid] = be1[tid] - m * sc;
    }
    __syncthreads();
    int row0 = blockIdx.x * 128;
    for (int e = tid; e < 4096; e += 512) {
        int r = e >> 5, s = (e & 31) * 4;
        float4 v = *(const float4*)&g_t[(size_t)(row0 + r) * 128 + s];
        float4 o;
        o.x = to_tf32(v.x * sScale[s] + sShift[s]);
        o.y = to_tf32(v.y * sScale[s + 1] + sShift[s + 1]);
        o.z = to_tf32(v.z * sScale[s + 2] + sShift[s + 2]);
        o.w = to_tf32(v.w * sScale[s + 3] + sShift[s + 3]);
        *(float4*)&BufA[r * AP_Q + s] = o;
    }

    int wid = tid >> 5, lane = tid & 31;
    int wr = wid >> 2, wc = wid & 3;
    int g = lane >> 2, t = lane & 3;

    #pragma unroll 1
    for (int widx = 0; widx < 3; widx++) {
        const float* W = (widx == 0) ? Wphi : (widx == 1) ? Wpsi : Walpha;
        float* out = (widx == 0) ? g_q : (widx == 1) ? g_kf : g_v;
        for (int e = tid; e < 4096; e += 512) {
            int k = e >> 5, s = (e & 31) * 4;
            float4 v = *(const float4*)&W[(size_t)k * 128 + s];
            float4 o = {to_tf32(v.x), to_tf32(v.y), to_tf32(v.z), to_tf32(v.w)};
            *(float4*)&BufW[k * P + s] = o;
        }
        __syncthreads();

        float acc[2][4][4];
        gemm_mma_q(BufA, BufW, acc, wr, wc, g, t);

        #pragma unroll
        for (int mi = 0; mi < 2; mi++) {
            int r0 = row0 + wr * 32 + mi * 16 + g;
            #pragma unroll
            for (int ni = 0; ni < 4; ni++) {
                int c0 = wc * 32 + ni * 8 + 2 * t;
                *(float2*)&out[(size_t)r0 * 128 + c0] =
                    make_float2(acc[mi][ni][0], acc[mi][ni][1]);
                *(float2*)&out[(size_t)(r0 + 8) * 128 + c0] =
                    make_float2(acc[mi][ni][2], acc[mi][ni][3]);
            }
        }
        __syncthreads();
    }
}

// ============================ fused per-point attention (mma tf32) ==============
__device__ __forceinline__ void ldW_async(float* dstBase, const float* src, int tid) {
    for (int e = tid; e < 4096; e += 512) {
        int r = e >> 5, c = (e & 31) * 4;
        cp16(dstBase + r * P + c, src + r * 128 + c);
    }
}

__global__ __launch_bounds__(512) void fused_kernel(const int* __restrict__ coords,
                                                    const float* __restrict__ Wd1,
                                                    const float* __restrict__ bd1,
                                                    const float* __restrict__ bd2,
                                                    const float* __restrict__ bg1,
                                                    const float* __restrict__ bg2) {
    extern __shared__ float sm[];
    float* BufA = sm;                      // [128][P] permuted-k A operand
    float* W0   = BufA + 128 * P;          // [128][P] [c][k'] weights
    float* W1   = W0 + 128 * P;            // [128][P]
    float* sQ   = W1 + 128 * P;            // [8][128]
    float* sRel = sQ + 8 * 128;            // [128][3]
    float* sWd1 = sRel + 128 * 3;          // [3][128]
    float* sBd1 = sWd1 + 384;              // [128]
    int*   sIdx = (int*)(sBd1 + 128);      // [128]

    int tid = threadIdx.x;
    int p0 = blockIdx.x * 8;
    int wid = tid >> 5, lane = tid & 31;
    int wr = wid >> 2, wc = wid & 3;
    int g = lane >> 2, t = lane & 3;

    // async weight loads: group1 = Wd2 -> W0, group2 = Wg1 -> W1
    ldW_async(W0, g_wtf, tid);           cp_commit();
    ldW_async(W1, g_wtf + 16384, tid);   cp_commit();

    if (tid < 128) {
        sIdx[tid] = g_idx[(size_t)p0 * KNN + tid];
        sBd1[tid] = bd1[tid];
    }
    if (tid < 384) sWd1[tid] = Wd1[tid];
    if (tid < 256) {
        int pp = tid >> 5, s = (tid & 31) * 4;
        *(float4*)&sQ[pp * 128 + s] = *(const float4*)&g_q[(size_t)(p0 + pp) * 128 + s];
    }
    __syncthreads();

    int r0_[2], r1_[2], gi0_[2], gi1_[2];
    #pragma unroll
    for (int mi = 0; mi < 2; mi++) {
        r0_[mi] = wr * 32 + mi * 16 + g;
        r1_[mi] = r0_[mi] + 8;
        gi0_[mi] = sIdx[r0_[mi]];
        gi1_[mi] = sIdx[r1_[mi]];
    }
    // prefetch kf gathers (consumed in epilogue1)
    float2 kf0[2][4], kf1[2][4];
    #pragma unroll
    for (int mi = 0; mi < 2; mi++)
        #pragma unroll
        for (int ni = 0; ni < 4; ni++) {
            int c0 = wc * 32 + ni * 8 + 2 * t;
            kf0[mi][ni] = *(const float2*)&g_kf[(size_t)gi0_[mi] * 128 + c0];
            kf1[mi][ni] = *(const float2*)&g_kf[(size_t)gi1_[mi] * 128 + c0];
        }

    if (tid < 128) {
        int i = p0 + (tid >> 4);
        int j = sIdx[tid];
        int4 ci = *(const int4*)&coords[(size_t)i * 4];
        int4 cj = *(const int4*)&coords[(size_t)j * 4];
        sRel[tid * 3 + 0] = (float)(ci.y - cj.y);
        sRel[tid * 3 + 1] = (float)(ci.z - cj.z);
        sRel[tid * 3 + 2] = (float)(ci.w - cj.w);
    }
    __syncthreads();

    // stage 1: BufA[r][perm(c)] <- tf32(relu(rel @ Wd1 + bd1))
    for (int e = tid; e < 128 * 128; e += 512) {
        int r = e >> 7, c = e & 127;
        float v = sBd1[c] + sRel[r * 3] * sWd1[c] + sRel[r * 3 + 1] * sWd1[128 + c]
                + sRel[r * 3 + 2] * sWd1[256 + c];
        BufA[r * P + permk(c)] = to_tf32(fmaxf(v, 0.f));
    }
    cp_wait<1>();          // Wd2 resident
    __syncthreads();

    // GEMM1: delta = h1 @ Wd2 + bd2  (registers)
    float dlt[2][4][4];
    gemm_mma_v(BufA, W0, dlt, wr, wc, g, t);
    #pragma unroll
    for (int mi = 0; mi < 2; mi++)
        #pragma unroll
        for (int ni = 0; ni < 4; ni++) {
            int c0 = wc * 32 + ni * 8 + 2 * t;
            float b0 = __ldg(&bd2[c0]), b1 = __ldg(&bd2[c0 + 1]);
            dlt[mi][ni][0] += b0; dlt[mi][ni][1] += b1;
            dlt[mi][ni][2] += b0; dlt[mi][ni][3] += b1;
        }
    __syncthreads();       // all GEMM1 reads of BufA/W0 complete

    // group3: Wg2 -> W0 (W0 now free)
    ldW_async(W0, g_wtf + 32768, tid);
    cp_commit();

    // epilogue1: BufA[r][perm(c)] <- tf32(q - kf + delta)
    #pragma unroll
    for (int mi = 0; mi < 2; mi++) {
        int pl = wr * 2 + mi;
        #pragma unroll
        for (int ni = 0; ni < 4; ni++) {
            int c0 = wc * 32 + ni * 8 + 2 * t;
            int ce = (c0 & ~7) | permk(c0 & 7);
            int co = (c0 & ~7) | permk((c0 & 7) + 1);
            float q0 = sQ[pl * 128 + c0], q1 = sQ[pl * 128 + c0 + 1];
            BufA[r0_[mi] * P + ce] = to_tf32(q0 - kf0[mi][ni].x + dlt[mi][ni][0]);
            BufA[r0_[mi] * P + co] = to_tf32(q1 - kf0[mi][ni].y + dlt[mi][ni][1]);
            BufA[r1_[mi] * P + ce] = to_tf32(q0 - kf1[mi][ni].x + dlt[mi][ni][2]);
            BufA[r1_[mi] * P + co] = to_tf32(q1 - kf1[mi][ni].y + dlt[mi][ni][3]);
        }
    }
    cp_wait<1>();          // Wg1 resident
    __syncthreads();

    // GEMM2: h2 = relu(apre @ Wg1 + bg1)
    float acc2[2][4][4];
    gemm_mma_v(BufA, W1, acc2, wr, wc, g, t);
    __syncthreads();       // GEMM2 reads of BufA complete
    #pragma unroll
    for (int mi = 0; mi < 2; mi++) {
        #pragma unroll
        for (int ni = 0; ni < 4; ni++) {
            int c0 = wc * 32 + ni * 8 + 2 * t;
            int ce = (c0 & ~7) | permk(c0 & 7);
            int co = (c0 & ~7) | permk((c0 & 7) + 1);
            float b0 = __ldg(&bg1[c0]), b1 = __ldg(&bg1[c0 + 1]);
            BufA[r0_[mi] * P + ce] = to_tf32(fmaxf(acc2[mi][ni][0] + b0, 0.f));
            BufA[r0_[mi] * P + co] = to_tf32(fmaxf(acc2[mi][ni][1] + b1, 0.f));
            BufA[r1_[mi] * P + ce] = to_tf32(fmaxf(acc2[mi][ni][2] + b0, 0.f));
            BufA[r1_[mi] * P + co] = to_tf32(fmaxf(acc2[mi][ni][3] + b1, 0.f));
        }
    }
    // prefetch v gathers (consumed in softmax)
    float2 v0r[2][4], v1r[2][4];
    #pragma unroll
    for (int mi = 0; mi < 2; mi++)
        #pragma unroll
        for (int ni = 0; ni < 4; ni++) {
            int c0 = wc * 32 + ni * 8 + 2 * t;
            v0r[mi][ni] = *(const float2*)&g_v[(size_t)gi0_[mi] * 128 + c0];
            v1r[mi][ni] = *(const float2*)&g_v[(size_t)gi1_[mi] * 128 + c0];
        }
    cp_wait<0>();          // Wg2 resident
    __syncthreads();

    // GEMM3: logits = h2 @ Wg2 (+bg2 below)
    gemm_mma_v(BufA, W0, acc2, wr, wc, g, t);

    // softmax over K + aggregate, in registers/shuffles
    #pragma unroll
    for (int mi = 0; mi < 2; mi++) {
        int pl = wr * 2 + mi;
        #pragma unroll
        for (int ni = 0; ni < 4; ni++) {
            int c0 = wc * 32 + ni * 8 + 2 * t;
            float b0 = __ldg(&bg2[c0]), b1 = __ldg(&bg2[c0 + 1]);
            float l00 = acc2[mi][ni][0] + b0, l01 = acc2[mi][ni][1] + b1;
            float l10 = acc2[mi][ni][2] + b0, l11 = acc2[mi][ni][3] + b1;
            float w00 = v0r[mi][ni].x + dlt[mi][ni][0], w01 = v0r[mi][ni].y + dlt[mi][ni][1];
            float w10 = v1r[mi][ni].x + dlt[mi][ni][2], w11 = v1r[mi][ni].y + dlt[mi][ni][3];

            float m0 = fmaxf(l00, l10);
            m0 = fmaxf(m0, __shfl_xor_sync(0xffffffffu, m0, 4));
            m0 = fmaxf(m0, __shfl_xor_sync(0xffffffffu, m0, 8));
            m0 = fmaxf(m0, __shfl_xor_sync(0xffffffffu, m0, 16));
            float m1 = fmaxf(l01, l11);
            m1 = fmaxf(m1, __shfl_xor_sync(0xffffffffu, m1, 4));
            m1 = fmaxf(m1, __shfl_xor_sync(0xffffffffu, m1, 8));
            m1 = fmaxf(m1, __shfl_xor_sync(0xffffffffu, m1, 16));

            float e00 = __expf(l00 - m0), e10 = __expf(l10 - m0);
            float e01 = __expf(l01 - m1), e11 = __expf(l11 - m1);
            float s0 = e00 + e10, s1 = e01 + e11;
            float a0 = e00 * w00 + e10 * w10;
            float a1 = e01 * w01 + e11 * w11;
            s0 += __shfl_xor_sync(0xffffffffu, s0, 4);
            s0 += __shfl_xor_sync(0xffffffffu, s0, 8);
            s0 += __shfl_xor_sync(0xffffffffu, s0, 16);
            s1 += __shfl_xor_sync(0xffffffffu, s1, 4);
            s1 += __shfl_xor_sync(0xffffffffu, s1, 8);
            s1 += __shfl_xor_sync(0xffffffffu, s1, 16);
            a0 += __shfl_xor_sync(0xffffffffu, a0, 4);
            a0 += __shfl_xor_sync(0xffffffffu, a0, 8);
            a0 += __shfl_xor_sync(0xffffffffu, a0, 16);
            a1 += __shfl_xor_sync(0xffffffffu, a1, 4);
            a1 += __shfl_xor_sync(0xffffffffu, a1, 8);
            a1 += __shfl_xor_sync(0xffffffffu, a1, 16);

            if (g == 0)
                *(float2*)&g_agg[(size_t)(p0 + pl) * 128 + c0] =
                    make_float2(a0 / s0, a1 / s1);
        }
    }
}

// ========== down-proj: out = agg @ W_down + b_down, fused BN partials ===========
__global__ __launch_bounds__(256) void down_kernel(const float* __restrict__ W,
                                                   const float* __restrict__ bias,
                                                   float* __restrict__ out) {
    __shared__ float As[16][128];
    __shared__ float Bs[16][64];
    __shared__ float redS[16][64];
    __shared__ float redSS[16][64];
    __shared__ double dS[4][64];
    __shared__ double dSS[4][64];
    __shared__ bool  sLast;
    int tid = threadIdx.x;
    int ty = tid >> 4, tx = tid & 15;
    int row0 = blockIdx.x * 128;
    float acc[8][4] = {};
    for (int kt = 0; kt < 128; kt += 16) {
        for (int e = tid; e < 512; e += 256) {
            int r = e >> 2, s = e & 3;
            float4 v = *(const float4*)&g_agg[(size_t)(row0 + r) * 128 + kt + s * 4];
            As[s * 4 + 0][r] = v.x; As[s * 4 + 1][r] = v.y;
            As[s * 4 + 2][r] = v.z; As[s * 4 + 3][r] = v.w;
        }
        if (tid < 256) {
            int k = tid >> 4, s = tid & 15;
            *(float4*)&Bs[k][s * 4] = *(const float4*)&W[(size_t)(kt + k) * 64 + s * 4];
        }
        __syncthreads();
        #pragma unroll
        for (int k = 0; k < 16; k++) {
            float4 a0 = *(const float4*)&As[k][ty * 8];
            float4 a1 = *(const float4*)&As[k][ty * 8 + 4];
            float4 b = *(const float4*)&Bs[k][tx * 4];
            float av[8] = {a0.x, a0.y, a0.z, a0.w, a1.x, a1.y, a1.z, a1.w};
            float bv[4] = {b.x, b.y, b.z, b.w};
            #pragma unroll
            for (int i = 0; i < 8; i++)
                #pragma unroll
                for (int j = 0; j < 4; j++)
                    acc[i][j] += av[i] * bv[j];
        }
        __syncthreads();
    }
    #pragma unroll
    for (int j = 0; j < 4; j++) {
        float b = __ldg(&bias[tx * 4 + j]);
        float s = 0.f, ss = 0.f;
        #pragma unroll
        for (int i = 0; i < 8; i++) {
            float v = acc[i][j] + b;
            out[(size_t)(row0 + ty * 8 + i) * 64 + tx * 4 + j] = v;
            s += v; ss += v * v;
        }
        redS[ty][tx * 4 + j] = s;
        redSS[ty][tx * 4 + j] = ss;
    }
    __syncthreads();
    if (tid < 64) {
        float s = 0.f, ss = 0.f;
        #pragma unroll
        for (int u = 0; u < 16; u++) { s += redS[u][tid]; ss += redSS[u][tid]; }
        g_part[blockIdx.x * 128 + tid]      = s;
        g_part[blockIdx.x * 128 + 64 + tid] = ss;
    }
    __threadfence();
    __syncthreads();
    if (tid == 0)
        sLast = (atomicAdd(&g_tick2, 1u) == gridDim.x - 1);
    __syncthreads();
    if (sLast) {
        int c = tid & 63, sub = tid >> 6;    // 4 subs x 64 channels
        double s = 0.0, ss = 0.0;
        for (int b = sub; b < 128; b += 4) {
            s  += (double)g_part[b * 128 + c];
            ss += (double)g_part[b * 128 + 64 + c];
        }
        dS[sub][c] = s; dSS[sub][c] = ss;
        __syncthreads();
        if (tid < 64) {
            double S = dS[0][tid] + dS[1][tid] + dS[2][tid] + dS[3][tid];
            double SS = dSS[0][tid] + dSS[1][tid] + dSS[2][tid] + dSS[3][tid];
            double m = S / (double)TOT;
            double var = SS / (double)TOT - m * m;
            g_stats[tid]      = (float)m;
            g_stats[64 + tid] = rsqrtf((float)var + 1e-5f);
        }
        if (tid == 0) g_tick2 = 0u;
    }
}

// ============================ final BN + residual ================================
__global__ __launch_bounds__(256) void final_kernel(const float* __restrict__ x,
                                                    const float* __restrict__ g2,
                                                    const float* __restrict__ be2,
                                                    float* __restrict__ out) {
    int e = blockIdx.x * 256 + threadIdx.x;
    if (e < TOT * IND) {
        int c = e & 63;
        float m = g_stats[c], is = g_stats[IND + c];
        out[e] = (out[e] - m) * is * g2[c] + be2[c] + x[e];
    }
}

// ============================ launch =============================================
extern "C" void kernel_launch(void* const* d_in, const int* in_sizes, int n_in,
                              void* d_out, int out_size) {
    const int*   coords  = (const int*)  d_in[0];
    const float* x       = (const float*)d_in[1];
    const float* W_top   = (const float*)d_in[2];
    const float* b_top   = (const float*)d_in[3];
    const float* g1      = (const float*)d_in[4];
    const float* be1     = (const float*)d_in[5];
    const float* W_phi   = (const float*)d_in[6];
    const float* W_psi   = (const float*)d_in[7];
    const float* W_alpha = (const float*)d_in[8];
    const float* Wd1     = (const float*)d_in[9];
    const float* bd1     = (const float*)d_in[10];
    const float* Wd2     = (const float*)d_in[11];
    const float* bd2     = (const float*)d_in[12];
    const float* Wg1     = (const float*)d_in[13];
    const float* bg1     = (const float*)d_in[14];
    const float* Wg2     = (const float*)d_in[15];
    const float* bg2     = (const float*)d_in[16];
    const float* W_down  = (const float*)d_in[17];
    const float* b_down  = (const float*)d_in[18];
    const float* g2      = (const float*)d_in[19];
    const float* be2     = (const float*)d_in[20];
    float* out = (float*)d_out;

    const size_t SMEM_F = (size_t)(3 * 128 * P + 8 * 128 + 128 * 3
                                   + 384 + 128 + 128) * 4;
    const size_t SMEM_Q = (size_t)(128 * AP_Q + 128 * P) * 4;
    cudaFuncSetAttribute(fused_kernel, cudaFuncAttributeMaxDynamicSharedMemorySize,
                         (int)SMEM_F);
    cudaFuncSetAttribute(qkv_kernel, cudaFuncAttributeMaxDynamicSharedMemorySize,
                         (int)SMEM_Q);

    conv_kernel<<<24, 512>>>(Wd2, Wg1, Wg2);
    ball_kernel<<<TOT / 128, 128>>>(coords);
    topproj_kernel<<<TOT / 128, 256>>>(x, W_top, b_top);
    qkv_kernel<<<TOT / 128, 512, SMEM_Q>>>(g1, be1, W_phi, W_psi, W_alpha);
    fused_kernel<<<TOT / 8, 512, SMEM_F>>>(coords, Wd1, bd1, bd2, bg1, bg2);
    down_kernel<<<TOT / 128, 256>>>(W_down, b_down, out);
    final_kernel<<<(TOT * IND + 255) / 256, 256>>>(x, g2, be2, out);
}

// round 9
// speedup vs baseline: 1.0269x; 1.0269x over previous
#include <cuda_runtime.h>
#include <cuda_bf16.h>
#include <cstdint>
#include <math.h>

#define TOT   16384
#define NPTS  4096
#define KNN   16
#define HD    128
#define IND   64
#define AP    132    // A-buffer pitch (scalar frag loads: banks g*4+t unique)
#define WP    136    // W-buffer pitch (banks t*8+g unique)

// ---------------- device scratch ------------------------------------------------
__device__ int   g_idx[TOT * KNN];
__device__ float g_t  [TOT * HD];
__device__ float g_q  [TOT * HD];
__device__ float g_kf [TOT * HD];
__device__ float g_v  [TOT * HD];
__device__ float g_agg[TOT * HD];
__device__ float g_part[128 * 2 * HD];
__device__ float g_stats[2 * HD];
__device__ float g_wtf[6 * HD * HD];   // tf32 k-major: Wd2,Wg1,Wg2,Wphi,Wpsi,Walpha
__device__ unsigned int g_tick1;
__device__ unsigned int g_tick2;

__device__ __forceinline__ float to_tf32(float x) {
    unsigned int r;
    asm("cvt.rna.tf32.f32 %0, %1;" : "=r"(r) : "f"(x));
    return __uint_as_float(r);
}

__device__ __forceinline__ void cp16(void* dst_smem, const void* src) {
    unsigned int d = (unsigned int)__cvta_generic_to_shared(dst_smem);
    asm volatile("cp.async.cg.shared.global [%0], [%1], 16;\n" :: "r"(d), "l"(src));
}
__device__ __forceinline__ void cp_commit() {
    asm volatile("cp.async.commit_group;\n");
}
template <int N>
__device__ __forceinline__ void cp_wait() {
    asm volatile("cp.async.wait_group %0;\n" :: "n"(N));
}

// ============== weight pre-convert: 6 matrices -> tf32, k-major [k][c] ===========
__global__ __launch_bounds__(512) void conv_kernel(const float* __restrict__ Wd2,
                                                   const float* __restrict__ Wg1,
                                                   const float* __restrict__ Wg2,
                                                   const float* __restrict__ Wphi,
                                                   const float* __restrict__ Wpsi,
                                                   const float* __restrict__ Walpha) {
    int e = blockIdx.x * 512 + threadIdx.x;            // one float4 each
    const float* srcs[6] = {Wd2, Wg1, Wg2, Wphi, Wpsi, Walpha};
    int m = e / 4096, o = (e % 4096) * 4;
    if (m < 6) {
        float4 v = *(const float4*)&srcs[m][o];
        float4 w = {to_tf32(v.x), to_tf32(v.y), to_tf32(v.z), to_tf32(v.w)};
        *(float4*)&g_wtf[m * 16384 + o] = w;
    }
}

// ============================ ball query =========================================
__global__ __launch_bounds__(128) void ball_kernel(const int* __restrict__ coords) {
    __shared__ int sP[NPTS];
    int b = (blockIdx.x * 128) / NPTS;
    int base = b * NPTS;
    for (int j = threadIdx.x; j < NPTS; j += 128) {
        int4 c = *(const int4*)&coords[(size_t)(base + j) * 4];
        sP[j] = c.y | (c.z << 8) | (c.w << 16);
    }
    __syncthreads();
    int qi = blockIdx.x * 128 + threadIdx.x;
    int me = sP[qi - base];
    int qx = me & 255, qy = (me >> 8) & 255, qz = me >> 16;
    int cnt = 0, first = 0;
    int* out = g_idx + (size_t)qi * KNN;
    #pragma unroll 8
    for (int j = 0; j < NPTS; j++) {
        int p = sP[j];
        int dx = qx - (p & 255);
        int dy = qy - ((p >> 8) & 255);
        int dz = qz - (p >> 16);
        int d2 = dx * dx + dy * dy + dz * dz;
        if (d2 <= 100) {
            int gj = base + j;
            out[cnt] = gj;
            if (cnt == 0) first = gj;
            cnt++;
            if (cnt == KNN) break;
        }
    }
    for (int k = cnt; k < KNN; k++) out[k] = first;
}

// ================ t = x @ W_top + b_top, fused BN partials + finalize ===========
__global__ __launch_bounds__(256) void topproj_kernel(const float* __restrict__ x,
                                                      const float* __restrict__ W,
                                                      const float* __restrict__ bias) {
    __shared__ float As[16][128];
    __shared__ float Bs[16][128];
    __shared__ float redS[16][128];
    __shared__ float redSS[16][128];
    __shared__ double dS[2][128];
    __shared__ double dSS[2][128];
    __shared__ bool  sLast;
    int tid = threadIdx.x;
    int ty = tid >> 4, tx = tid & 15;
    int row0 = blockIdx.x * 128;
    float acc[8][8] = {};
    for (int kt = 0; kt < 64; kt += 16) {
        for (int e = tid; e < 512; e += 256) {
            int r = e >> 2, s = e & 3;
            float4 v = *(const float4*)&x[(size_t)(row0 + r) * 64 + kt + s * 4];
            As[s * 4 + 0][r] = v.x; As[s * 4 + 1][r] = v.y;
            As[s * 4 + 2][r] = v.z; As[s * 4 + 3][r] = v.w;
        }
        for (int e = tid; e < 512; e += 256) {
            int k = e >> 5, s = e & 31;
            *(float4*)&Bs[k][s * 4] = *(const float4*)&W[(size_t)(kt + k) * 128 + s * 4];
        }
        __syncthreads();
        #pragma unroll
        for (int k = 0; k < 16; k++) {
            float4 a0 = *(const float4*)&As[k][ty * 8];
            float4 a1 = *(const float4*)&As[k][ty * 8 + 4];
            float4 b0 = *(const float4*)&Bs[k][tx * 8];
            float4 b1 = *(const float4*)&Bs[k][tx * 8 + 4];
            float av[8] = {a0.x, a0.y, a0.z, a0.w, a1.x, a1.y, a1.z, a1.w};
            float bv[8] = {b0.x, b0.y, b0.z, b0.w, b1.x, b1.y, b1.z, b1.w};
            #pragma unroll
            for (int i = 0; i < 8; i++)
                #pragma unroll
                for (int j = 0; j < 8; j++)
                    acc[i][j] += av[i] * bv[j];
        }
        __syncthreads();
    }
    #pragma unroll
    for (int j = 0; j < 8; j++) {
        float b = __ldg(&bias[tx * 8 + j]);
        float s = 0.f, ss = 0.f;
        #pragma unroll
        for (int i = 0; i < 8; i++) {
            float v = acc[i][j] + b;
            g_t[(size_t)(row0 + ty * 8 + i) * 128 + tx * 8 + j] = v;
            s += v; ss += v * v;
        }
        redS[ty][tx * 8 + j] = s;
        redSS[ty][tx * 8 + j] = ss;
    }
    __syncthreads();
    if (tid < 128) {
        float s = 0.f, ss = 0.f;
        #pragma unroll
        for (int u = 0; u < 16; u++) { s += redS[u][tid]; ss += redSS[u][tid]; }
        g_part[blockIdx.x * 256 + tid]       = s;
        g_part[blockIdx.x * 256 + 128 + tid] = ss;
    }
    __threadfence();
    __syncthreads();
    if (tid == 0)
        sLast = (atomicAdd(&g_tick1, 1u) == gridDim.x - 1);
    __syncthreads();
    if (sLast) {
        int c = tid & 127, sub = tid >> 7;   // 2 subs x 128 channels
        double s = 0.0, ss = 0.0;
        for (int b = sub; b < 128; b += 2) {
            s  += (double)g_part[b * 256 + c];
            ss += (double)g_part[b * 256 + 128 + c];
        }
        dS[sub][c] = s; dSS[sub][c] = ss;
        __syncthreads();
        if (tid < 128) {
            double S = dS[0][tid] + dS[1][tid];
            double SS = dSS[0][tid] + dSS[1][tid];
            double m = S / (double)TOT;
            double var = SS / (double)TOT - m * m;
            g_stats[tid]       = (float)m;
            g_stats[128 + tid] = rsqrtf((float)var + 1e-5f);
        }
        if (tid == 0) g_tick1 = 0u;
    }
}

// ============================ tf32 mma GEMM core =================================
// 128x128x128; 16 warps; warp tile 32x32 (wr=wid>>2, wc=wid&3); m16n8k8.
// A [128][AP] row-major tf32; W [128][WP] k-major tf32.
__device__ __forceinline__ void gemm_mma(const float* __restrict__ A,
                                         const float* __restrict__ W,
                                         float acc[2][4][4],
                                         int wr, int wc, int g, int t) {
    #pragma unroll
    for (int i = 0; i < 2; i++)
        #pragma unroll
        for (int j = 0; j < 4; j++)
            #pragma unroll
            for (int r = 0; r < 4; r++) acc[i][j][r] = 0.f;
    #pragma unroll 4
    for (int kk = 0; kk < 16; kk++) {
        const int k0 = kk * 8;
        unsigned int a[2][4];
        #pragma unroll
        for (int mi = 0; mi < 2; mi++) {
            const float* ap = A + (size_t)(wr * 32 + mi * 16 + g) * AP + k0 + t;
            a[mi][0] = __float_as_uint(ap[0]);
            a[mi][1] = __float_as_uint(ap[8 * AP]);
            a[mi][2] = __float_as_uint(ap[4]);
            a[mi][3] = __float_as_uint(ap[8 * AP + 4]);
        }
        #pragma unroll
        for (int ni = 0; ni < 4; ni++) {
            const float* bp = W + (size_t)(k0 + t) * WP + wc * 32 + ni * 8 + g;
            unsigned int b0 = __float_as_uint(bp[0]);
            unsigned int b1 = __float_as_uint(bp[4 * WP]);
            #pragma unroll
            for (int mi = 0; mi < 2; mi++) {
                asm volatile(
                    "mma.sync.aligned.m16n8k8.row.col.f32.tf32.tf32.f32 "
                    "{%0,%1,%2,%3}, {%4,%5,%6,%7}, {%8,%9}, {%0,%1,%2,%3};\n"
                    : "+f"(acc[mi][ni][0]), "+f"(acc[mi][ni][1]),
                      "+f"(acc[mi][ni][2]), "+f"(acc[mi][ni][3])
                    : "r"(a[mi][0]), "r"(a[mi][1]), "r"(a[mi][2]), "r"(a[mi][3]),
                      "r"(b0), "r"(b1));
            }
        }
    }
}

// shared helper: async copy one 128x128 tf32 weight (k-major) into [128][WP] smem
__device__ __forceinline__ void ldW_async(float* dstBase, const float* src, int tid,
                                          int nthreads) {
    for (int e = tid; e < 4096; e += nthreads) {
        int r = e >> 5, c = (e & 31) * 4;
        cp16(dstBase + r * WP + c, src + r * 128 + c);
    }
}

// ============== q,kf,v = normalize(t) @ {W_phi,W_psi,W_alpha} (mma tf32) =========
// One block per 128-row slab; weights double-buffered via cp.async from g_wtf.
__global__ __launch_bounds__(512) void qkv_kernel(const float* __restrict__ g1v,
                                                  const float* __restrict__ be1) {
    extern __shared__ float sm[];
    float* BufA = sm;                    // [128][AP]
    float* W0   = BufA + 128 * AP;       // [128][WP]
    float* W1   = W0 + 128 * WP;         // [128][WP]
    __shared__ float sScale[128], sShift[128];
    int tid = threadIdx.x;

    // prefetch Wphi -> W0, Wpsi -> W1
    ldW_async(W0, g_wtf + 3 * 16384, tid, 512);  cp_commit();
    ldW_async(W1, g_wtf + 4 * 16384, tid, 512);  cp_commit();

    if (tid < 128) {
        float m = g_stats[tid], is = g_stats[128 + tid];
        float sc = is * g1v[tid];
        sScale[tid] = sc;
        sShift[tid] = be1[tid] - m * sc;
    }
    __syncthreads();
    int row0 = blockIdx.x * 128;
    for (int e = tid; e < 4096; e += 512) {
        int r = e >> 5, s = (e & 31) * 4;
        float4 v = *(const float4*)&g_t[(size_t)(row0 + r) * 128 + s];
        float4 o;
        o.x = to_tf32(v.x * sScale[s] + sShift[s]);
        o.y = to_tf32(v.y * sScale[s + 1] + sShift[s + 1]);
        o.z = to_tf32(v.z * sScale[s + 2] + sShift[s + 2]);
        o.w = to_tf32(v.w * sScale[s + 3] + sShift[s + 3]);
        *(float4*)&BufA[r * AP + s] = o;
    }

    int wid = tid >> 5, lane = tid & 31;
    int wr = wid >> 2, wc = wid & 3;
    int g = lane >> 2, t = lane & 3;

    #pragma unroll 1
    for (int widx = 0; widx < 3; widx++) {
        float* out = (widx == 0) ? g_q : (widx == 1) ? g_kf : g_v;
        const float* Wb = (widx == 1) ? W1 : W0;
        if (widx < 2) { cp_wait<1>(); } else { cp_wait<0>(); }
        __syncthreads();

        float acc[2][4][4];
        gemm_mma(BufA, Wb, acc, wr, wc, g, t);
        __syncthreads();   // all reads of Wb done before any overwrite

        if (widx == 0) {   // prefetch Walpha -> W0 (free after GEMM0)
            ldW_async(W0, g_wtf + 5 * 16384, tid, 512);
            cp_commit();
        }

        #pragma unroll
        for (int mi = 0; mi < 2; mi++) {
            int r0 = row0 + wr * 32 + mi * 16 + g;
            #pragma unroll
            for (int ni = 0; ni < 4; ni++) {
                int c0 = wc * 32 + ni * 8 + 2 * t;
                *(float2*)&out[(size_t)r0 * 128 + c0] =
                    make_float2(acc[mi][ni][0], acc[mi][ni][1]);
                *(float2*)&out[(size_t)(r0 + 8) * 128 + c0] =
                    make_float2(acc[mi][ni][2], acc[mi][ni][3]);
            }
        }
    }
}

// ============================ fused per-point attention (mma tf32) ==============
// 8 points/block, 512 threads. cp.async double-buffered tf32 weights from g_wtf;
// kf/v gathers prefetched into registers; delta in regs; shuffle softmax.
__global__ __launch_bounds__(512) void fused_kernel(const int* __restrict__ coords,
                                                    const float* __restrict__ Wd1,
                                                    const float* __restrict__ bd1,
                                                    const float* __restrict__ bd2,
                                                    const float* __restrict__ bg1,
                                                    const float* __restrict__ bg2) {
    extern __shared__ float sm[];
    float* BufA = sm;                      // [128][AP]
    float* W0   = BufA + 128 * AP;         // [128][WP]
    float* W1   = W0 + 128 * WP;           // [128][WP]
    float* sQ   = W1 + 128 * WP;           // [8][128]
    float* sRel = sQ + 8 * 128;            // [128][3]
    float* sWd1 = sRel + 128 * 3;          // [3][128]
    float* sBd1 = sWd1 + 384;              // [128]
    int*   sIdx = (int*)(sBd1 + 128);      // [128]

    int tid = threadIdx.x;
    int p0 = blockIdx.x * 8;
    int wid = tid >> 5, lane = tid & 31;
    int wr = wid >> 2, wc = wid & 3;
    int g = lane >> 2, t = lane & 3;

    // async weight loads: group1 = Wd2 -> W0, group2 = Wg1 -> W1
    ldW_async(W0, g_wtf, tid, 512);           cp_commit();
    ldW_async(W1, g_wtf + 16384, tid, 512);   cp_commit();

    if (tid < 128) {
        sIdx[tid] = g_idx[(size_t)p0 * KNN + tid];
        sBd1[tid] = bd1[tid];
    }
    if (tid < 384) sWd1[tid] = Wd1[tid];
    if (tid < 256) {
        int pp = tid >> 5, s = (tid & 31) * 4;
        *(float4*)&sQ[pp * 128 + s] = *(const float4*)&g_q[(size_t)(p0 + pp) * 128 + s];
    }
    __syncthreads();

    int r0_[2], r1_[2], gi0_[2], gi1_[2];
    #pragma unroll
    for (int mi = 0; mi < 2; mi++) {
        r0_[mi] = wr * 32 + mi * 16 + g;
        r1_[mi] = r0_[mi] + 8;
        gi0_[mi] = sIdx[r0_[mi]];
        gi1_[mi] = sIdx[r1_[mi]];
    }
    // prefetch kf gathers (consumed in epilogue1)
    float2 kf0[2][4], kf1[2][4];
    #pragma unroll
    for (int mi = 0; mi < 2; mi++)
        #pragma unroll
        for (int ni = 0; ni < 4; ni++) {
            int c0 = wc * 32 + ni * 8 + 2 * t;
            kf0[mi][ni] = *(const float2*)&g_kf[(size_t)gi0_[mi] * 128 + c0];
            kf1[mi][ni] = *(const float2*)&g_kf[(size_t)gi1_[mi] * 128 + c0];
        }

    if (tid < 128) {
        int i = p0 + (tid >> 4);
        int j = sIdx[tid];
        int4 ci = *(const int4*)&coords[(size_t)i * 4];
        int4 cj = *(const int4*)&coords[(size_t)j * 4];
        sRel[tid * 3 + 0] = (float)(ci.y - cj.y);
        sRel[tid * 3 + 1] = (float)(ci.z - cj.z);
        sRel[tid * 3 + 2] = (float)(ci.w - cj.w);
    }
    __syncthreads();

    // stage 1: BufA <- tf32(relu(rel @ Wd1 + bd1))
    for (int e = tid; e < 128 * 128; e += 512) {
        int r = e >> 7, c = e & 127;
        float v = sBd1[c] + sRel[r * 3] * sWd1[c] + sRel[r * 3 + 1] * sWd1[128 + c]
                + sRel[r * 3 + 2] * sWd1[256 + c];
        BufA[r * AP + c] = to_tf32(fmaxf(v, 0.f));
    }
    cp_wait<1>();          // Wd2 resident
    __syncthreads();

    // GEMM1: delta = h1 @ Wd2 + bd2  (registers)
    float dlt[2][4][4];
    gemm_mma(BufA, W0, dlt, wr, wc, g, t);
    #pragma unroll
    for (int mi = 0; mi < 2; mi++)
        #pragma unroll
        for (int ni = 0; ni < 4; ni++) {
            int c0 = wc * 32 + ni * 8 + 2 * t;
            float b0 = __ldg(&bd2[c0]), b1 = __ldg(&bd2[c0 + 1]);
            dlt[mi][ni][0] += b0; dlt[mi][ni][1] += b1;
            dlt[mi][ni][2] += b0; dlt[mi][ni][3] += b1;
        }
    __syncthreads();       // all GEMM1 reads of BufA/W0 complete

    // group3: Wg2 -> W0 (W0 now free)
    ldW_async(W0, g_wtf + 32768, tid, 512);
    cp_commit();

    // epilogue1: BufA <- tf32(q - kf + delta)
    #pragma unroll
    for (int mi = 0; mi < 2; mi++) {
        int pl = wr * 2 + mi;
        #pragma unroll
        for (int ni = 0; ni < 4; ni++) {
            int c0 = wc * 32 + ni * 8 + 2 * t;
            float q0 = sQ[pl * 128 + c0], q1 = sQ[pl * 128 + c0 + 1];
            *(float2*)&BufA[r0_[mi] * AP + c0] =
                make_float2(to_tf32(q0 - kf0[mi][ni].x + dlt[mi][ni][0]),
                            to_tf32(q1 - kf0[mi][ni].y + dlt[mi][ni][1]));
            *(float2*)&BufA[r1_[mi] * AP + c0] =
                make_float2(to_tf32(q0 - kf1[mi][ni].x + dlt[mi][ni][2]),
                            to_tf32(q1 - kf1[mi][ni].y + dlt[mi][ni][3]));
        }
    }
    cp_wait<1>();          // Wg1 resident
    __syncthreads();

    // GEMM2: h2 = relu(apre @ Wg1 + bg1)
    float acc2[2][4][4];
    gemm_mma(BufA, W1, acc2, wr, wc, g, t);
    __syncthreads();       // GEMM2 reads of BufA complete
    #pragma unroll
    for (int mi = 0; mi < 2; mi++) {
        #pragma unroll
        for (int ni = 0; ni < 4; ni++) {
            int c0 = wc * 32 + ni * 8 + 2 * t;
            float b0 = __ldg(&bg1[c0]), b1 = __ldg(&bg1[c0 + 1]);
            *(float2*)&BufA[r0_[mi] * AP + c0] =
                make_float2(to_tf32(fmaxf(acc2[mi][ni][0] + b0, 0.f)),
                            to_tf32(fmaxf(acc2[mi][ni][1] + b1, 0.f)));
            *(float2*)&BufA[r1_[mi] * AP + c0] =
                make_float2(to_tf32(fmaxf(acc2[mi][ni][2] + b0, 0.f)),
                            to_tf32(fmaxf(acc2[mi][ni][3] + b1, 0.f)));
        }
    }
    // prefetch v gathers (consumed in softmax)
    float2 v0r[2][4], v1r[2][4];
    #pragma unroll
    for (int mi = 0; mi < 2; mi++)
        #pragma unroll
        for (int ni = 0; ni < 4; ni++) {
            int c0 = wc * 32 + ni * 8 + 2 * t;
            v0r[mi][ni] = *(const float2*)&g_v[(size_t)gi0_[mi] * 128 + c0];
            v1r[mi][ni] = *(const float2*)&g_v[(size_t)gi1_[mi] * 128 + c0];
        }
    cp_wait<0>();          // Wg2 resident
    __syncthreads();

    // GEMM3: logits = h2 @ Wg2 (+bg2 below)
    gemm_mma(BufA, W0, acc2, wr, wc, g, t);

    // softmax over K + aggregate, in registers/shuffles
    #pragma unroll
    for (int mi = 0; mi < 2; mi++) {
        int pl = wr * 2 + mi;
        #pragma unroll
        for (int ni = 0; ni < 4; ni++) {
            int c0 = wc * 32 + ni * 8 + 2 * t;
            float b0 = __ldg(&bg2[c0]), b1 = __ldg(&bg2[c0 + 1]);
            float l00 = acc2[mi][ni][0] + b0, l01 = acc2[mi][ni][1] + b1;
            float l10 = acc2[mi][ni][2] + b0, l11 = acc2[mi][ni][3] + b1;
            float w00 = v0r[mi][ni].x + dlt[mi][ni][0], w01 = v0r[mi][ni].y + dlt[mi][ni][1];
            float w10 = v1r[mi][ni].x + dlt[mi][ni][2], w11 = v1r[mi][ni].y + dlt[mi][ni][3];

            float m0 = fmaxf(l00, l10);
            m0 = fmaxf(m0, __shfl_xor_sync(0xffffffffu, m0, 4));
            m0 = fmaxf(m0, __shfl_xor_sync(0xffffffffu, m0, 8));
            m0 = fmaxf(m0, __shfl_xor_sync(0xffffffffu, m0, 16));
            float m1 = fmaxf(l01, l11);
            m1 = fmaxf(m1, __shfl_xor_sync(0xffffffffu, m1, 4));
            m1 = fmaxf(m1, __shfl_xor_sync(0xffffffffu, m1, 8));
            m1 = fmaxf(m1, __shfl_xor_sync(0xffffffffu, m1, 16));

            float e00 = __expf(l00 - m0), e10 = __expf(l10 - m0);
            float e01 = __expf(l01 - m1), e11 = __expf(l11 - m1);
            float s0 = e00 + e10, s1 = e01 + e11;
            float a0 = e00 * w00 + e10 * w10;
            float a1 = e01 * w01 + e11 * w11;
            s0 += __shfl_xor_sync(0xffffffffu, s0, 4);
            s0 += __shfl_xor_sync(0xffffffffu, s0, 8);
            s0 += __shfl_xor_sync(0xffffffffu, s0, 16);
            s1 += __shfl_xor_sync(0xffffffffu, s1, 4);
            s1 += __shfl_xor_sync(0xffffffffu, s1, 8);
            s1 += __shfl_xor_sync(0xffffffffu, s1, 16);
            a0 += __shfl_xor_sync(0xffffffffu, a0, 4);
            a0 += __shfl_xor_sync(0xffffffffu, a0, 8);
            a0 += __shfl_xor_sync(0xffffffffu, a0, 16);
            a1 += __shfl_xor_sync(0xffffffffu, a1, 4);
            a1 += __shfl_xor_sync(0xffffffffu, a1, 8);
            a1 += __shfl_xor_sync(0xffffffffu, a1, 16);

            if (g == 0)
                *(float2*)&g_agg[(size_t)(p0 + pl) * 128 + c0] =
                    make_float2(a0 / s0, a1 / s1);
        }
    }
}

// ========== down-proj: out = agg @ W_down + b_down, fused BN partials ===========
__global__ __launch_bounds__(256) void down_kernel(const float* __restrict__ W,
                                                   const float* __restrict__ bias,
                                                   float* __restrict__ out) {
    __shared__ float As[16][128];
    __shared__ float Bs[16][64];
    __shared__ float redS[16][64];
    __shared__ float redSS[16][64];
    __shared__ double dS[4][64];
    __shared__ double dSS[4][64];
    __shared__ bool  sLast;
    int tid = threadIdx.x;
    int ty = tid >> 4, tx = tid & 15;
    int row0 = blockIdx.x * 128;
    float acc[8][4] = {};
    for (int kt = 0; kt < 128; kt += 16) {
        for (int e = tid; e < 512; e += 256) {
            int r = e >> 2, s = e & 3;
            float4 v = *(const float4*)&g_agg[(size_t)(row0 + r) * 128 + kt + s * 4];
            As[s * 4 + 0][r] = v.x; As[s * 4 + 1][r] = v.y;
            As[s * 4 + 2][r] = v.z; As[s * 4 + 3][r] = v.w;
        }
        if (tid < 256) {
            int k = tid >> 4, s = tid & 15;
            *(float4*)&Bs[k][s * 4] = *(const float4*)&W[(size_t)(kt + k) * 64 + s * 4];
        }
        __syncthreads();
        #pragma unroll
        for (int k = 0; k < 16; k++) {
            float4 a0 = *(const float4*)&As[k][ty * 8];
            float4 a1 = *(const float4*)&As[k][ty * 8 + 4];
            float4 b = *(const float4*)&Bs[k][tx * 4];
            float av[8] = {a0.x, a0.y, a0.z, a0.w, a1.x, a1.y, a1.z, a1.w};
            float bv[4] = {b.x, b.y, b.z, b.w};
            #pragma unroll
            for (int i = 0; i < 8; i++)
                #pragma unroll
                for (int j = 0; j < 4; j++)
                    acc[i][j] += av[i] * bv[j];
        }
        __syncthreads();
    }
    #pragma unroll
    for (int j = 0; j < 4; j++) {
        float b = __ldg(&bias[tx * 4 + j]);
        float s = 0.f, ss = 0.f;
        #pragma unroll
        for (int i = 0; i < 8; i++) {
            float v = acc[i][j] + b;
            out[(size_t)(row0 + ty * 8 + i) * 64 + tx * 4 + j] = v;
            s += v; ss += v * v;
        }
        redS[ty][tx * 4 + j] = s;
        redSS[ty][tx * 4 + j] = ss;
    }
    __syncthreads();
    if (tid < 64) {
        float s = 0.f, ss = 0.f;
        #pragma unroll
        for (int u = 0; u < 16; u++) { s += redS[u][tid]; ss += redSS[u][tid]; }
        g_part[blockIdx.x * 128 + tid]      = s;
        g_part[blockIdx.x * 128 + 64 + tid] = ss;
    }
    __threadfence();
    __syncthreads();
    if (tid == 0)
        sLast = (atomicAdd(&g_tick2, 1u) == gridDim.x - 1);
    __syncthreads();
    if (sLast) {
        int c = tid & 63, sub = tid >> 6;    // 4 subs x 64 channels
        double s = 0.0, ss = 0.0;
        for (int b = sub; b < 128; b += 4) {
            s  += (double)g_part[b * 128 + c];
            ss += (double)g_part[b * 128 + 64 + c];
        }
        dS[sub][c] = s; dSS[sub][c] = ss;
        __syncthreads();
        if (tid < 64) {
            double S = dS[0][tid] + dS[1][tid] + dS[2][tid] + dS[3][tid];
            double SS = dSS[0][tid] + dSS[1][tid] + dSS[2][tid] + dSS[3][tid];
            double m = S / (double)TOT;
            double var = SS / (double)TOT - m * m;
            g_stats[tid]      = (float)m;
            g_stats[64 + tid] = rsqrtf((float)var + 1e-5f);
        }
        if (tid == 0) g_tick2 = 0u;
    }
}

// ============================ final BN + residual ================================
__global__ __launch_bounds__(256) void final_kernel(const float* __restrict__ x,
                                                    const float* __restrict__ g2,
                                                    const float* __restrict__ be2,
                                                    float* __restrict__ out) {
    int e = blockIdx.x * 256 + threadIdx.x;
    if (e < TOT * IND) {
        int c = e & 63;
        float m = g_stats[c], is = g_stats[IND + c];
        out[e] = (out[e] - m) * is * g2[c] + be2[c] + x[e];
    }
}

// ============================ launch =============================================
extern "C" void kernel_launch(void* const* d_in, const int* in_sizes, int n_in,
                              void* d_out, int out_size) {
    const int*   coords  = (const int*)  d_in[0];
    const float* x       = (const float*)d_in[1];
    const float* W_top   = (const float*)d_in[2];
    const float* b_top   = (const float*)d_in[3];
    const float* g1      = (const float*)d_in[4];
    const float* be1     = (const float*)d_in[5];
    const float* W_phi   = (const float*)d_in[6];
    const float* W_psi   = (const float*)d_in[7];
    const float* W_alpha = (const float*)d_in[8];
    const float* Wd1     = (const float*)d_in[9];
    const float* bd1     = (const float*)d_in[10];
    const float* Wd2     = (const float*)d_in[11];
    const float* bd2     = (const float*)d_in[12];
    const float* Wg1     = (const float*)d_in[13];
    const float* bg1     = (const float*)d_in[14];
    const float* Wg2     = (const float*)d_in[15];
    const float* bg2     = (const float*)d_in[16];
    const float* W_down  = (const float*)d_in[17];
    const float* b_down  = (const float*)d_in[18];
    const float* g2      = (const float*)d_in[19];
    const float* be2     = (const float*)d_in[20];
    float* out = (float*)d_out;

    const size_t SMEM_F = (size_t)(128 * AP + 2 * 128 * WP + 8 * 128 + 128 * 3
                                   + 384 + 128 + 128) * 4;
    const size_t SMEM_Q = (size_t)(128 * AP + 2 * 128 * WP) * 4;
    cudaFuncSetAttribute(fused_kernel, cudaFuncAttributeMaxDynamicSharedMemorySize,
                         (int)SMEM_F);
    cudaFuncSetAttribute(qkv_kernel, cudaFuncAttributeMaxDynamicSharedMemorySize,
                         (int)SMEM_Q);

    conv_kernel<<<48, 512>>>(Wd2, Wg1, Wg2, W_phi, W_psi, W_alpha);
    ball_kernel<<<TOT / 128, 128>>>(coords);
    topproj_kernel<<<TOT / 128, 256>>>(x, W_top, b_top);
    qkv_kernel<<<TOT / 128, 512, SMEM_Q>>>(g1, be1);
    fused_kernel<<<TOT / 8, 512, SMEM_F>>>(coords, Wd1, bd1, bd2, bg1, bg2);
    down_kernel<<<TOT / 128, 256>>>(W_down, b_down, out);
    final_kernel<<<(TOT * IND + 255) / 256, 256>>>(x, g2, be2, out);
}